// round 4
// baseline (speedup 1.0000x reference)
#include <cuda_runtime.h>
#include <cuda_bf16.h>

// ---------------- problem constants ----------------
#define BB    32
#define NNc   6
#define BN    192          // BB*NNc
#define INCH  768
#define FHc   4
#define FWc   6
#define PXc   24           // FHc*FWc
#define OCH   105          // D + C
#define DDc   41
#define CCc   64
#define KSP   4            // K-split for conv
#define KC    192          // INCH / KSP
#define NXc   200
#define NYc   200
#define GRID_PER_B (CCc*NXc*NYc)          // 2,560,000
#define FINAL_ELEMS ((size_t)BB*GRID_PER_B) // 81,920,000
#define NPTS  (BN*DDc*PXc)                // 188,928

// ---------------- scratch (static device arrays; no allocations) ----------------
__device__ float g_part [KSP*BN*PXc*OCH];   // conv partial sums   (~7.7 MB)
__device__ float g_depth[BN*PXc*DDc];       // softmax(depth)
__device__ float g_feat [BN*PXc*CCc];       // feat, channel-contiguous per pixel
__device__ float g_comb [BN*9];             // rots @ inv(intrins)

// ---------------- kernel 0: combine matrices ----------------
__global__ void k_comb(const float* __restrict__ rots, const float* __restrict__ intr) {
    int t = threadIdx.x;
    if (t >= BN) return;
    const float* K = intr + t*9;
    float a=K[0],b=K[1],c=K[2],d=K[3],e=K[4],f=K[5],g=K[6],h=K[7],i=K[8];
    float A  =  (e*i - f*h);
    float Bc = -(d*i - f*g);
    float Cc =  (d*h - e*g);
    float det = a*A + b*Bc + c*Cc;
    float idet = 1.0f/det;
    float inv[9];
    inv[0]=A*idet;            inv[1]=-(b*i-c*h)*idet;  inv[2]= (b*f-c*e)*idet;
    inv[3]=Bc*idet;           inv[4]= (a*i-c*g)*idet;  inv[5]=-(a*f-c*d)*idet;
    inv[6]=Cc*idet;           inv[7]=-(a*h-b*g)*idet;  inv[8]= (a*e-b*d)*idet;
    const float* R = rots + t*9;
    #pragma unroll
    for (int r = 0; r < 3; ++r)
        #pragma unroll
        for (int cc = 0; cc < 3; ++cc)
            g_comb[t*9 + r*3 + cc] =
                R[r*3+0]*inv[0*3+cc] + R[r*3+1]*inv[1*3+cc] + R[r*3+2]*inv[2*3+cc];
}

// ---------------- kernel 1: 1x1 conv, K-split partial GEMM ----------------
// grid = BN*KSP blocks, 162 threads: thread tile = 4 px x 4 outch
__global__ __launch_bounds__(162) void k_conv(const float* __restrict__ x,
                                              const float* __restrict__ wmat) {
    const int bn = blockIdx.x >> 2;
    const int ks = blockIdx.x & 3;
    __shared__ float xs[KC*PXc];     // 4608 floats = 18.0 KB
    __shared__ float ws[108*69];     // 7452 floats = 29.1 KB (pitch 69: conflict-free)
    const int tid = threadIdx.x;
    const int pxg = tid % 6;         // pixel group (4 px each)
    const int og  = tid / 6;         // out-channel group 0..26 (4 each)

    // load this split's x slab: contiguous 4608 floats
    const float4* xg = (const float4*)(x + (size_t)bn*INCH*PXc + (size_t)ks*KC*PXc);
    for (int i = tid; i < KC*PXc/4; i += 162) ((float4*)xs)[i] = xg[i];

    float acc[4][4];
    #pragma unroll
    for (int j = 0; j < 4; ++j)
        #pragma unroll
        for (int i = 0; i < 4; ++i) acc[j][i] = 0.0f;

    for (int sub = 0; sub < 3; ++sub) {           // 3 x 64 channels
        __syncthreads();
        // load w chunk [108 o][64 c], coalesced rows of conv_w
        for (int i = tid; i < 108*16; i += 162) {
            int o  = i >> 4;
            int c4 = i & 15;
            float4 v = make_float4(0.f,0.f,0.f,0.f);
            if (o < OCH)
                v = *(const float4*)(wmat + (size_t)o*INCH + ks*KC + sub*64 + c4*4);
            int base = o*69 + c4*4;
            ws[base+0]=v.x; ws[base+1]=v.y; ws[base+2]=v.z; ws[base+3]=v.w;
        }
        __syncthreads();
        #pragma unroll 4
        for (int c = 0; c < 64; ++c) {
            float4 xv = *(const float4*)&xs[(sub*64 + c)*PXc + pxg*4];
            #pragma unroll
            for (int j = 0; j < 4; ++j) {
                float wv = ws[(og*4 + j)*69 + c];
                acc[j][0] += wv*xv.x; acc[j][1] += wv*xv.y;
                acc[j][2] += wv*xv.z; acc[j][3] += wv*xv.w;
            }
        }
    }

    // write partials (no atomics: per-split buffer)
    #pragma unroll
    for (int j = 0; j < 4; ++j) {
        int o = og*4 + j;
        if (o >= OCH) continue;
        #pragma unroll
        for (int i = 0; i < 4; ++i) {
            int px = pxg*4 + i;
            g_part[(( (size_t)ks*BN + bn)*PXc + px)*OCH + o] = acc[j][i];
        }
    }
}

// ---------------- kernel 2: reduce splits + bias + softmax + split depth/feat ----------------
// one warp per pixel; 4 warps/block; grid 1152
__global__ __launch_bounds__(128) void k_softmax(const float* __restrict__ bias,
                                                 float* __restrict__ out_logit) {
    const int warp = threadIdx.x >> 5;
    const int lane = threadIdx.x & 31;
    const int pid  = blockIdx.x*4 + warp;       // 0..4607
    const int bn   = pid / PXc;
    const int px   = pid % PXc;

    float y[4];
    #pragma unroll
    for (int k = 0; k < 4; ++k) {
        int id = lane + 32*k;
        float v = 0.0f;
        if (id < OCH) {
            v = bias[id];
            #pragma unroll
            for (int ks = 0; ks < KSP; ++ks)
                v += g_part[(((size_t)ks*BN + bn)*PXc + px)*OCH + id];
        }
        y[k] = v;
    }

    // softmax over depth channels [0,41)
    float m = y[0];
    if (lane < 9) m = fmaxf(m, y[1]);
    #pragma unroll
    for (int s = 16; s; s >>= 1) m = fmaxf(m, __shfl_xor_sync(0xffffffffu, m, s));
    float e0 = expf(y[0] - m);
    float e1 = (lane < 9) ? expf(y[1] - m) : 0.0f;
    float ssum = e0 + e1;
    #pragma unroll
    for (int s = 16; s; s >>= 1) ssum += __shfl_xor_sync(0xffffffffu, ssum, s);

    // depth_logit output: layout ((bn*41+d)*4+h)*6+w = (bn*41+d)*24 + px
    out_logit[((size_t)bn*DDc + lane)*PXc + px] = y[0];
    if (lane < 9) out_logit[((size_t)bn*DDc + lane + 32)*PXc + px] = y[1];

    size_t pbase = (size_t)(bn*PXc + px);
    g_depth[pbase*DDc + lane] = e0 / ssum;
    if (lane < 9) g_depth[pbase*DDc + lane + 32] = e1 / ssum;

    // feat channels [41,105) -> [0,64)
    if (lane >= 9) g_feat[pbase*CCc + (lane + 32 - 41)] = y[1];
    g_feat[pbase*CCc + (lane + 64 - 41)] = y[2];
    if (lane < 9) g_feat[pbase*CCc + (lane + 96 - 41)] = y[3];
}

// ---------------- kernel 3: geometry + voxel scatter ----------------
// one warp per frustum point; lanes cover 64 channels (2 each)
__global__ __launch_bounds__(256) void k_scatter(const float* __restrict__ trans,
                                                 float* __restrict__ out) {
    const int p    = blockIdx.x*8 + (threadIdx.x >> 5);
    const int lane = threadIdx.x & 31;

    const int bn = p / (DDc*PXc);
    const int r  = p % (DDc*PXc);
    const int d  = r / PXc;
    const int px = r % PXc;
    const int h  = px / FWc;
    const int w  = px % FWc;

    // frustum (match numpy linspace: double step, cast to f32)
    const float dsv = 4.0f + (float)d;
    const float xsv = (float)((double)w * (199.0/5.0));
    const float ysv = (float)((double)h * (149.0/3.0));
    const float p0 = xsv * dsv;
    const float p1 = ysv * dsv;
    const float p2 = dsv;

    const float* M = g_comb + bn*9;
    const float* T = trans  + bn*3;
    float gx = M[0]*p0 + M[1]*p1 + M[2]*p2 + T[0];
    float gy = M[3]*p0 + M[4]*p1 + M[5]*p2 + T[1];
    float gz = M[6]*p0 + M[7]*p1 + M[8]*p2 + T[2];

    // truncation toward zero == .astype(int32)
    int ix = (int)((gx + 50.0f) / 0.5f);
    int iy = (int)((gy + 50.0f) / 0.5f);
    int iz = (int)((gz + 10.0f) / 20.0f);
    if (ix < 0 || ix >= NXc || iy < 0 || iy >= NYc || iz != 0) return;

    const int b = bn / NNc;
    const size_t pbase = (size_t)(bn*PXc + px);
    const float dep = g_depth[pbase*DDc + d];
    const float* fptr = g_feat + pbase*CCc;
    const float f0 = fptr[lane];
    const float f1 = fptr[lane + 32];

    const size_t cellbase = (size_t)b*GRID_PER_B + (size_t)ix*NYc + iy;
    atomicAdd(out + cellbase + (size_t)lane        * (NXc*NYc), dep * f0);
    atomicAdd(out + cellbase + (size_t)(lane + 32) * (NXc*NYc), dep * f1);
}

// ---------------- launch ----------------
extern "C" void kernel_launch(void* const* d_in, const int* in_sizes, int n_in,
                              void* d_out, int out_size) {
    const float* x     = (const float*)d_in[0];
    const float* rots  = (const float*)d_in[1];
    const float* trans = (const float*)d_in[2];
    const float* intr  = (const float*)d_in[3];
    const float* cw    = (const float*)d_in[4];
    const float* cb    = (const float*)d_in[5];
    float* out = (float*)d_out;

    // zero the dense BEV output (327 MB)
    cudaMemsetAsync(out, 0, FINAL_ELEMS * sizeof(float), 0);

    k_comb   <<<1, 192>>>(rots, intr);
    k_conv   <<<BN*KSP, 162>>>(x, cw);
    k_softmax<<<(BN*PXc)/4, 128>>>(cb, out + FINAL_ELEMS);
    k_scatter<<<NPTS/8, 256>>>(trans, out);
}

// round 8
// speedup vs baseline: 1.2031x; 1.2031x over previous
#include <cuda_runtime.h>
#include <cuda_bf16.h>

// ---------------- problem constants ----------------
#define BB    32
#define NNc   6
#define BN    192
#define INCH  768
#define FHc   4
#define FWc   6
#define PXc   24
#define OCH   105
#define DDc   41
#define CCc   64
#define KSP   4
#define KC    192
#define NXc   200
#define NYc   200
#define GRID_PER_B (CCc*NXc*NYc)            // 2,560,000
#define FINAL_ELEMS ((size_t)BB*GRID_PER_B) // 81,920,000
#define NPTS  (BN*DDc*PXc)                  // 188,928

// tiling for BEV accumulation: 2 ix-rows per tile
#define TROWS 2
#define TILES_PER_B (NXc/TROWS)             // 100
#define NTILES (BB*TILES_PER_B)             // 3200
#define BINCAP 6144                         // >= max 5904 points per batch
#define CPAD 65                             // smem channel pitch (bank-conflict-free)
#define TILE_FLOATS (TROWS*NYc*CPAD)        // 26000

// ---------------- scratch ----------------
__device__ float g_part [KSP*BN*PXc*OCH];
__device__ float g_depth[BN*PXc*DDc];
__device__ float g_feat [BN*PXc*CCc];
__device__ float g_comb [BN*9];
__device__ int   g_bincnt[NTILES];
__device__ unsigned int g_bins[(size_t)NTILES*BINCAP];   // 78.6 MB records

// ---------------- kernel 0: combine matrices + zero bin counters ----------------
__global__ void k_comb(const float* __restrict__ rots, const float* __restrict__ intr) {
    int t = blockIdx.x*blockDim.x + threadIdx.x;
    if (t < NTILES) g_bincnt[t] = 0;
    if (t >= BN) return;
    const float* K = intr + t*9;
    float a=K[0],b=K[1],c=K[2],d=K[3],e=K[4],f=K[5],g=K[6],h=K[7],i=K[8];
    float A  =  (e*i - f*h);
    float Bc = -(d*i - f*g);
    float Cc =  (d*h - e*g);
    float idet = 1.0f/(a*A + b*Bc + c*Cc);
    float inv[9];
    inv[0]=A*idet;   inv[1]=-(b*i-c*h)*idet;  inv[2]= (b*f-c*e)*idet;
    inv[3]=Bc*idet;  inv[4]= (a*i-c*g)*idet;  inv[5]=-(a*f-c*d)*idet;
    inv[6]=Cc*idet;  inv[7]=-(a*h-b*g)*idet;  inv[8]= (a*e-b*d)*idet;
    const float* R = rots + t*9;
    #pragma unroll
    for (int r = 0; r < 3; ++r)
        #pragma unroll
        for (int cc = 0; cc < 3; ++cc)
            g_comb[t*9 + r*3 + cc] =
                R[r*3+0]*inv[0*3+cc] + R[r*3+1]*inv[1*3+cc] + R[r*3+2]*inv[2*3+cc];
}

// ---------------- kernel 1: 1x1 conv, K-split partial GEMM ----------------
__global__ __launch_bounds__(162) void k_conv(const float* __restrict__ x,
                                              const float* __restrict__ wmat) {
    const int bn = blockIdx.x >> 2;
    const int ks = blockIdx.x & 3;
    __shared__ float xs[KC*PXc];
    __shared__ float ws[108*69];
    const int tid = threadIdx.x;
    const int pxg = tid % 6;
    const int og  = tid / 6;

    const float4* xg = (const float4*)(x + (size_t)bn*INCH*PXc + (size_t)ks*KC*PXc);
    for (int i = tid; i < KC*PXc/4; i += 162) ((float4*)xs)[i] = xg[i];

    float acc[4][4];
    #pragma unroll
    for (int j = 0; j < 4; ++j)
        #pragma unroll
        for (int i = 0; i < 4; ++i) acc[j][i] = 0.0f;

    for (int sub = 0; sub < 3; ++sub) {
        __syncthreads();
        for (int i = tid; i < 108*16; i += 162) {
            int o  = i >> 4;
            int c4 = i & 15;
            float4 v = make_float4(0.f,0.f,0.f,0.f);
            if (o < OCH)
                v = *(const float4*)(wmat + (size_t)o*INCH + ks*KC + sub*64 + c4*4);
            int base = o*69 + c4*4;
            ws[base+0]=v.x; ws[base+1]=v.y; ws[base+2]=v.z; ws[base+3]=v.w;
        }
        __syncthreads();
        #pragma unroll 4
        for (int c = 0; c < 64; ++c) {
            float4 xv = *(const float4*)&xs[(sub*64 + c)*PXc + pxg*4];
            #pragma unroll
            for (int j = 0; j < 4; ++j) {
                float wv = ws[(og*4 + j)*69 + c];
                acc[j][0] += wv*xv.x; acc[j][1] += wv*xv.y;
                acc[j][2] += wv*xv.z; acc[j][3] += wv*xv.w;
            }
        }
    }

    #pragma unroll
    for (int j = 0; j < 4; ++j) {
        int o = og*4 + j;
        if (o >= OCH) continue;
        #pragma unroll
        for (int i = 0; i < 4; ++i) {
            int px = pxg*4 + i;
            g_part[(( (size_t)ks*BN + bn)*PXc + px)*OCH + o] = acc[j][i];
        }
    }
}

// ---------------- kernel 2: reduce + bias + softmax + split ----------------
__global__ __launch_bounds__(128) void k_softmax(const float* __restrict__ bias,
                                                 float* __restrict__ out_logit) {
    const int warp = threadIdx.x >> 5;
    const int lane = threadIdx.x & 31;
    const int pid  = blockIdx.x*4 + warp;
    const int bn   = pid / PXc;
    const int px   = pid % PXc;

    float y[4];
    #pragma unroll
    for (int k = 0; k < 4; ++k) {
        int id = lane + 32*k;
        float v = 0.0f;
        if (id < OCH) {
            v = bias[id];
            #pragma unroll
            for (int ks = 0; ks < KSP; ++ks)
                v += g_part[(((size_t)ks*BN + bn)*PXc + px)*OCH + id];
        }
        y[k] = v;
    }

    float m = y[0];
    if (lane < 9) m = fmaxf(m, y[1]);
    #pragma unroll
    for (int s = 16; s; s >>= 1) m = fmaxf(m, __shfl_xor_sync(0xffffffffu, m, s));
    float e0 = expf(y[0] - m);
    float e1 = (lane < 9) ? expf(y[1] - m) : 0.0f;
    float ssum = e0 + e1;
    #pragma unroll
    for (int s = 16; s; s >>= 1) ssum += __shfl_xor_sync(0xffffffffu, ssum, s);

    out_logit[((size_t)bn*DDc + lane)*PXc + px] = y[0];
    if (lane < 9) out_logit[((size_t)bn*DDc + lane + 32)*PXc + px] = y[1];

    size_t pbase = (size_t)(bn*PXc + px);
    g_depth[pbase*DDc + lane] = e0 / ssum;
    if (lane < 9) g_depth[pbase*DDc + lane + 32] = e1 / ssum;

    if (lane >= 9) g_feat[pbase*CCc + (lane + 32 - 41)] = y[1];
    g_feat[pbase*CCc + (lane + 64 - 41)] = y[2];
    if (lane < 9) g_feat[pbase*CCc + (lane + 96 - 41)] = y[3];
}

// ---------------- kernel 3: geometry + binning (one thread per point) ----------------
__global__ __launch_bounds__(256) void k_bin(const float* __restrict__ trans) {
    const int p = blockIdx.x*256 + threadIdx.x;
    if (p >= NPTS) return;

    const int bn = p / (DDc*PXc);
    const int r  = p % (DDc*PXc);
    const int d  = r / PXc;
    const int px = r % PXc;
    const int h  = px / FWc;
    const int w  = px % FWc;

    const float dsv = 4.0f + (float)d;
    const float xsv = (float)((double)w * (199.0/5.0));
    const float ysv = (float)((double)h * (149.0/3.0));
    const float p0 = xsv * dsv;
    const float p1 = ysv * dsv;
    const float p2 = dsv;

    const float* M = g_comb + bn*9;
    const float* T = trans  + bn*3;
    float gx = M[0]*p0 + M[1]*p1 + M[2]*p2 + T[0];
    float gy = M[3]*p0 + M[4]*p1 + M[5]*p2 + T[1];
    float gz = M[6]*p0 + M[7]*p1 + M[8]*p2 + T[2];

    // truncation toward zero == .astype(int32)
    int ix = (int)((gx + 50.0f) / 0.5f);
    int iy = (int)((gy + 50.0f) / 0.5f);
    int iz = (int)((gz + 10.0f) / 20.0f);
    if (ix < 0 || ix >= NXc || iy < 0 || iy >= NYc || iz != 0) return;

    const int b    = bn / NNc;
    const int tile = b*TILES_PER_B + (ix >> 1);
    const int cell = (ix & 1)*NYc + iy;             // < 400
    const int pd   = (bn*PXc + px)*DDc + d;         // 18 bits

    int pos = atomicAdd(&g_bincnt[tile], 1);
    g_bins[(size_t)tile*BINCAP + pos] = ((unsigned)pd << 9) | (unsigned)cell;
}

// ---------------- kernel 4: per-tile SMEM accumulate + full write-out ----------------
__global__ __launch_bounds__(1024) void k_tile(float* __restrict__ out) {
    extern __shared__ float s[];                    // TILE_FLOATS
    const int tile = blockIdx.x;
    const int b    = tile / TILES_PER_B;
    const int tix  = tile % TILES_PER_B;            // ix base = tix*2
    const int tid  = threadIdx.x;
    const int lane = tid & 31;
    const int wid  = tid >> 5;

    // zero strip
    for (int i = tid; i < TILE_FLOATS/4; i += 1024)
        ((float4*)s)[i] = make_float4(0.f,0.f,0.f,0.f);
    __syncthreads();

    // accumulate this tile's points (warp per record, lanes = channels)
    const int cnt = g_bincnt[tile];
    const unsigned* rec = g_bins + (size_t)tile*BINCAP;
    for (int i = wid; i < cnt; i += 32) {
        unsigned e = rec[i];
        int cell = (int)(e & 511u);
        int pd   = (int)(e >> 9);
        float dep = g_depth[pd];
        int pb = pd / DDc;                          // bn*24+px
        const float* fp = g_feat + (size_t)pb*CCc;
        float f0 = fp[lane];
        float f1 = fp[lane + 32];
        atomicAdd(&s[cell*CPAD + lane],      dep*f0);
        atomicAdd(&s[cell*CPAD + lane + 32], dep*f1);
    }
    __syncthreads();

    // write full strip (zeros included): out[((b*64+c))*40000 + ix*200 + iy]
    // j indexes float4 groups: TROWS*CCc*(NYc/4) = 6400
    for (int j = tid; j < TROWS*CCc*(NYc/4); j += 1024) {
        int q   = j % (NYc/4);                      // iy group
        int pth = j / (NYc/4);                      // (row, c)
        int c   = pth & 63;
        int row = pth >> 6;
        int iy0 = q*4;
        int sb  = (row*NYc + iy0)*CPAD + c;
        float4 v;
        v.x = s[sb];
        v.y = s[sb + CPAD];
        v.z = s[sb + 2*CPAD];
        v.w = s[sb + 3*CPAD];
        int ix = tix*TROWS + row;
        *(float4*)(out + ((size_t)(b*CCc + c)*NXc + ix)*NYc + iy0) = v;
    }
}

// ---------------- launch ----------------
extern "C" void kernel_launch(void* const* d_in, const int* in_sizes, int n_in,
                              void* d_out, int out_size) {
    const float* x     = (const float*)d_in[0];
    const float* rots  = (const float*)d_in[1];
    const float* trans = (const float*)d_in[2];
    const float* intr  = (const float*)d_in[3];
    const float* cw    = (const float*)d_in[4];
    const float* cb    = (const float*)d_in[5];
    float* out = (float*)d_out;

    static int smem_set = 0;
    if (!smem_set) {
        cudaFuncSetAttribute(k_tile, cudaFuncAttributeMaxDynamicSharedMemorySize,
                             TILE_FLOATS*sizeof(float));
        smem_set = 1;
    }

    k_comb   <<<(NTILES+255)/256, 256>>>(rots, intr);
    k_conv   <<<BN*KSP, 162>>>(x, cw);
    k_softmax<<<(BN*PXc)/4, 128>>>(cb, out + FINAL_ELEMS);
    k_bin    <<<(NPTS+255)/256, 256>>>(trans);
    k_tile   <<<NTILES, 1024, TILE_FLOATS*sizeof(float)>>>(out);
}